// round 1
// baseline (speedup 1.0000x reference)
#include <cuda_runtime.h>
#include <math_constants.h>

#define NPTS    4096
#define KNN     20
#define CO      64
#define CTA     256

__global__ __launch_bounds__(CTA, 8)
void edgeconv_kernel(const float* __restrict__ x,      // (B,3,N)
                     const float* __restrict__ W,      // (64,6)
                     const float* __restrict__ gamma_, // (64)
                     const float* __restrict__ beta_,  // (64)
                     const float* __restrict__ mean_,  // (64)
                     const float* __restrict__ var_,   // (64)
                     float* __restrict__ out)          // (B,64,N)
{
    __shared__ float dist[NPTS];
    __shared__ float rval[8];
    __shared__ int   ridx[8];
    __shared__ int   knn[KNN];
    __shared__ float nbr[KNN][3];

    const int b   = blockIdx.y;
    const int n   = blockIdx.x;
    const int tid = threadIdx.x;

    const float* xb0 = x + (size_t)b * 3 * NPTS;
    const float* xb1 = xb0 + NPTS;
    const float* xb2 = xb1 + NPTS;

    const float qx = xb0[n], qy = xb1[n], qz = xb2[n];
    const float xxq = qx*qx + qy*qy + qz*qz;

    // ---- phase 1: pairwise "similarity" pd = 2*q.p - |q|^2 - |p|^2 (= -dist^2)
    #pragma unroll 4
    for (int p = tid; p < NPTS; p += CTA) {
        float px = xb0[p], py = xb1[p], pz = xb2[p];
        float dot = qx*px + qy*py + qz*pz;
        float xxp = px*px + py*py + pz*pz;
        dist[p] = 2.0f*dot - xxq - xxp;
    }
    __syncthreads();

    // ---- phase 2: 20 rounds of block-wide argmax (lowest index wins ties)
    for (int k = 0; k < KNN; k++) {
        float best = -CUDART_INF_F;
        int   bi   = NPTS;
        #pragma unroll 4
        for (int p = tid; p < NPTS; p += CTA) {
            float v = dist[p];
            if (v > best) { best = v; bi = p; }   // strided ascending -> first hit = lowest idx
        }
        #pragma unroll
        for (int off = 16; off; off >>= 1) {
            float ov = __shfl_down_sync(0xffffffffu, best, off);
            int   oi = __shfl_down_sync(0xffffffffu, bi,   off);
            if (ov > best || (ov == best && oi < bi)) { best = ov; bi = oi; }
        }
        if ((tid & 31) == 0) { rval[tid >> 5] = best; ridx[tid >> 5] = bi; }
        __syncthreads();
        if (tid == 0) {
            float bb = rval[0]; int ii = ridx[0];
            #pragma unroll
            for (int w = 1; w < 8; w++) {
                float ov = rval[w]; int oi = ridx[w];
                if (ov > bb || (ov == bb && oi < ii)) { bb = ov; ii = oi; }
            }
            knn[k]   = ii;
            dist[ii] = -CUDART_INF_F;   // remove winner
        }
        __syncthreads();
    }

    // ---- phase 3: gather neighbor coordinates
    if (tid < KNN * 3) {
        int k = tid / 3, c = tid % 3;
        nbr[k][c] = x[(size_t)b * 3 * NPTS + (size_t)c * NPTS + knn[k]];
    }
    __syncthreads();

    // ---- phase 4: edge MLP (6 -> 64) + folded BN + leaky relu + max over K
    if (tid < CO) {
        const int o = tid;
        const float w0 = W[o*6+0], w1 = W[o*6+1], w2 = W[o*6+2];
        const float w3 = W[o*6+3], w4 = W[o*6+4], w5 = W[o*6+5];
        const float inv   = gamma_[o] / sqrtf(var_[o] + 1e-5f);
        const float shift = beta_[o] - mean_[o] * inv;
        const float cpart = qx*w3 + qy*w4 + qz*w5;  // center half, constant over k

        float m = -CUDART_INF_F;
        #pragma unroll
        for (int k = 0; k < KNN; k++) {
            float ex = nbr[k][0] - qx;
            float ey = nbr[k][1] - qy;
            float ez = nbr[k][2] - qz;
            float y  = ex*w0 + ey*w1 + ez*w2 + cpart;
            y = y * inv + shift;
            y = (y >= 0.0f) ? y : 0.2f * y;
            m = fmaxf(m, y);
        }
        out[(size_t)b * CO * NPTS + (size_t)o * NPTS + n] = m;
    }
}

extern "C" void kernel_launch(void* const* d_in, const int* in_sizes, int n_in,
                              void* d_out, int out_size)
{
    const float* x      = (const float*)d_in[0];
    const float* W      = (const float*)d_in[1];
    const float* gamma_ = (const float*)d_in[2];
    const float* beta_  = (const float*)d_in[3];
    const float* mean_  = (const float*)d_in[4];
    const float* var_   = (const float*)d_in[5];
    float* out = (float*)d_out;

    dim3 grid(NPTS, 8);
    edgeconv_kernel<<<grid, CTA>>>(x, W, gamma_, beta_, mean_, var_, out);
}

// round 2
// speedup vs baseline: 2.1422x; 2.1422x over previous
#include <cuda_runtime.h>

#define NPTS 4096
#define NB   8
#define KNN  20
#define CO   64
#define CTA  256
#define SLOTS (NPTS / CTA)   // 16 points per thread

__device__ float4 g_xp[NB * NPTS];   // packed {x, y, z, -0.5*|p|^2}

__global__ void prep_kernel(const float* __restrict__ x)
{
    int idx = blockIdx.x * blockDim.x + threadIdx.x;
    if (idx >= NB * NPTS) return;
    int b = idx >> 12, p = idx & (NPTS - 1);
    const float* xb = x + (size_t)b * 3 * NPTS;
    float px = xb[p], py = xb[NPTS + p], pz = xb[2 * NPTS + p];
    g_xp[idx] = make_float4(px, py, pz, -0.5f * (px*px + py*py + pz*pz));
}

// monotone float->uint mapping: preserves < ordering, larger float -> larger uint
__device__ __forceinline__ unsigned mono(float f)
{
    unsigned b = __float_as_uint(f);
    return b ^ (unsigned)(((int)b >> 31) | 0x80000000);
}

__global__ __launch_bounds__(CTA)
void edgeconv_kernel(const float* __restrict__ W,      // (64,6)
                     const float* __restrict__ gamma_, // (64)
                     const float* __restrict__ beta_,
                     const float* __restrict__ mean_,
                     const float* __restrict__ var_,
                     float* __restrict__ out)          // (B,64,N)
{
    __shared__ unsigned keysu[NPTS];   // monotone keys, indexed by point id
    __shared__ unsigned wv[8];         // per-warp cached max key
    __shared__ int      wi[8];         // per-warp cached argmax (point id)
    __shared__ int      knn_s[KNN];
    __shared__ float4   nbr[KNN];
    __shared__ int      win_s;

    const int b    = blockIdx.y;
    const int n    = blockIdx.x;
    const int tid  = threadIdx.x;
    const int lane = tid & 31;
    const int wid  = tid >> 5;

    const float4* __restrict__ xp = g_xp + (size_t)b * NPTS;
    const float4 q = xp[n];            // qw = -0.5*|q|^2

    // ---- phase 1: half-distance keys + per-thread cached max ----
    unsigned bu = 0; int bp = 0x7fffffff;
    #pragma unroll
    for (int i = 0; i < SLOTS; i++) {
        int p = i * CTA + tid;
        float4 v = xp[p];
        float s = q.w + v.w;                           // -(|q|^2+|p|^2)/2
        s = fmaf(q.x, v.x, fmaf(q.y, v.y, fmaf(q.z, v.z, s)));  // = pd/2
        unsigned u = mono(s);
        keysu[p] = u;
        if (u > bu) { bu = u; bp = p; }                // strict > : lowest idx on tie
    }

    // initial per-warp reduce of cached maxima
    {
        unsigned ru = bu; int rp = bp;
        #pragma unroll
        for (int off = 16; off; off >>= 1) {
            unsigned uo = __shfl_down_sync(0xffffffffu, ru, off);
            int      po = __shfl_down_sync(0xffffffffu, rp, off);
            if (uo > ru || (uo == ru && po < rp)) { ru = uo; rp = po; }
        }
        if (lane == 0) { wv[wid] = ru; wi[wid] = rp; }
    }
    __syncthreads();

    // ---- phase 2: 20 rounds, incremental argmax ----
    for (int k = 0; k < KNN; k++) {
        // warp 0: reduce the 8 cached warp maxima
        if (wid == 0) {
            unsigned u = 0; int pi = 0x7fffffff;
            if (lane < 8) { u = wv[lane]; pi = wi[lane]; }
            #pragma unroll
            for (int off = 4; off; off >>= 1) {
                unsigned uo = __shfl_down_sync(0xffffffffu, u, off);
                int      po = __shfl_down_sync(0xffffffffu, pi, off);
                if (uo > u || (uo == u && po < pi)) { u = uo; pi = po; }
            }
            if (lane == 0) { win_s = pi; knn_s[k] = pi; }
        }
        __syncthreads();

        const int widx  = win_s;
        const int owner = widx & (CTA - 1);

        // only the winner's warp repairs its cached state
        if (wid == (owner >> 5)) {
            if (tid == owner) keysu[widx] = 0;         // remove winner (0 < any real key)
            __syncwarp();
            // cooperative rescan of owner's 16 slots
            unsigned u2 = 0; int p2 = 0x7fffffff;
            if (lane < SLOTS) { p2 = lane * CTA + owner; u2 = keysu[p2]; }
            #pragma unroll
            for (int off = 8; off; off >>= 1) {
                unsigned uo = __shfl_down_sync(0xffffffffu, u2, off);
                int      po = __shfl_down_sync(0xffffffffu, p2, off);
                if (uo > u2 || (uo == u2 && po < p2)) { u2 = uo; p2 = po; }
            }
            u2 = __shfl_sync(0xffffffffu, u2, 0);
            p2 = __shfl_sync(0xffffffffu, p2, 0);
            if (tid == owner) { bu = u2; bp = p2; }    // refresh owner's cache
            // re-reduce this warp's cached maxima
            unsigned ru = bu; int rp = bp;
            #pragma unroll
            for (int off = 16; off; off >>= 1) {
                unsigned uo = __shfl_down_sync(0xffffffffu, ru, off);
                int      po = __shfl_down_sync(0xffffffffu, rp, off);
                if (uo > ru || (uo == ru && po < rp)) { ru = uo; rp = po; }
            }
            if (lane == 0) { wv[wid] = ru; wi[wid] = rp; }
        }
        __syncthreads();
    }

    // ---- phase 3: gather neighbor coords ----
    if (tid < KNN) nbr[tid] = xp[knn_s[tid]];
    __syncthreads();

    // ---- phase 4: edge MLP (6->64) + folded BN + leaky relu + max over K ----
    if (tid < CO) {
        const int o = tid;
        const float w0 = W[o*6+0], w1 = W[o*6+1], w2 = W[o*6+2];
        const float w3 = W[o*6+3], w4 = W[o*6+4], w5 = W[o*6+5];
        const float inv   = gamma_[o] * rsqrtf(var_[o] + 1e-5f);
        const float shift = beta_[o] - mean_[o] * inv;
        const float cpart = q.x*w3 + q.y*w4 + q.z*w5;

        float m = -3.4028235e38f;
        #pragma unroll
        for (int k = 0; k < KNN; k++) {
            float ex = nbr[k].x - q.x;
            float ey = nbr[k].y - q.y;
            float ez = nbr[k].z - q.z;
            float y  = fmaf(ex, w0, fmaf(ey, w1, fmaf(ez, w2, cpart)));
            y = fmaf(y, inv, shift);
            y = (y >= 0.0f) ? y : 0.2f * y;
            m = fmaxf(m, y);
        }
        out[(size_t)b * CO * NPTS + (size_t)o * NPTS + n] = m;
    }
}

extern "C" void kernel_launch(void* const* d_in, const int* in_sizes, int n_in,
                              void* d_out, int out_size)
{
    const float* x      = (const float*)d_in[0];
    const float* W      = (const float*)d_in[1];
    const float* gamma_ = (const float*)d_in[2];
    const float* beta_  = (const float*)d_in[3];
    const float* mean_  = (const float*)d_in[4];
    const float* var_   = (const float*)d_in[5];
    float* out = (float*)d_out;

    prep_kernel<<<(NB * NPTS + 255) / 256, 256>>>(x);
    dim3 grid(NPTS, NB);
    edgeconv_kernel<<<grid, CTA>>>(W, gamma_, beta_, mean_, var_, out);
}

// round 3
// speedup vs baseline: 3.1029x; 1.4485x over previous
#include <cuda_runtime.h>

#define NPTS 4096
#define NB   8
#define KNN  20
#define CO   64
#define CTA  256
#define SLOTS (NPTS / CTA)   // 16 keys per thread

__device__ float4 g_xp[NB * NPTS];   // packed {x, y, z, -0.5*|p|^2}

__global__ void prep_kernel(const float* __restrict__ x)
{
    int idx = blockIdx.x * blockDim.x + threadIdx.x;
    if (idx >= NB * NPTS) return;
    int b = idx >> 12, p = idx & (NPTS - 1);
    const float* xb = x + (size_t)b * 3 * NPTS;
    float px = xb[p], py = xb[NPTS + p], pz = xb[2 * NPTS + p];
    g_xp[idx] = make_float4(px, py, pz, -0.5f * (px*px + py*py + pz*pz));
}

// monotone float->uint: preserves ordering, larger float -> larger uint
__device__ __forceinline__ unsigned mono(float f)
{
    unsigned b = __float_as_uint(f);
    return b ^ (unsigned)(((int)b >> 31) | 0x80000000);
}

__global__ __launch_bounds__(CTA)
void edgeconv_kernel(const float* __restrict__ W,      // (64,6)
                     const float* __restrict__ gamma_,
                     const float* __restrict__ beta_,
                     const float* __restrict__ mean_,
                     const float* __restrict__ var_,
                     float* __restrict__ out)          // (B,64,N)
{
    __shared__ unsigned keysu[NPTS];
    __shared__ int      hist[256];
    __shared__ int      knn_s[KNN];
    __shared__ float4   nbr[KNN];
    __shared__ int      tie_idx[64];
    __shared__ unsigned tie_key[64];
    __shared__ int      s_cntW, s_cntT, s_need;
    __shared__ unsigned s_prefix;

    const int b    = blockIdx.y;
    const int n    = blockIdx.x;
    const int tid  = threadIdx.x;
    const int lane = tid & 31;
    const int wid  = tid >> 5;

    const float4* __restrict__ xp = g_xp + (size_t)b * NPTS;
    const float4 q = xp[n];

    hist[tid] = 0;
    if (tid == 0) { s_cntW = 0; s_cntT = 0; s_need = KNN; s_prefix = 0; }
    __syncthreads();

    // ---- phase 1: keys (pd/2, monotone uint) + level-0 histogram (bits 31:24)
    #pragma unroll
    for (int i = 0; i < SLOTS; i++) {
        int p = i * CTA + tid;
        float4 v = xp[p];
        float s = q.w + v.w;
        s = fmaf(q.x, v.x, fmaf(q.y, v.y, fmaf(q.z, v.z, s)));
        unsigned u = mono(s);
        keysu[p] = u;
        int bin = (int)(u >> 24);
        unsigned mk = __match_any_sync(0xffffffffu, bin);
        if ((__ffs(mk) - 1) == lane) atomicAdd(&hist[bin], __popc(mk));
    }
    __syncthreads();

    // ---- phase 2: 3-level radix select (8 bits per level)
    #pragma unroll
    for (int lvl = 0; lvl < 3; lvl++) {
        // warp 0: suffix-scan the 256-bin histogram from the top
        if (wid == 0) {
            int base = 255 - lane * 8;      // lane chunks in descending bin order
            int c[8];
            int s = 0;
            #pragma unroll
            for (int j = 0; j < 8; j++) { c[j] = hist[base - j]; s += c[j]; }
            int cum = s;
            #pragma unroll
            for (int off = 1; off < 32; off <<= 1) {
                int t = __shfl_up_sync(0xffffffffu, cum, off);
                if (lane >= off) cum += t;
            }
            int needv = s_need;
            __syncwarp();
            int cumBefore = cum - s;
            if (cumBefore < needv && needv <= cum) {
                int acc = cumBefore;
                int bsel = base;
                #pragma unroll
                for (int j = 0; j < 8; j++) {
                    if (acc + c[j] >= needv) { bsel = base - j; break; }
                    acc += c[j];
                }
                s_prefix = (s_prefix << 8) | (unsigned)bsel;
                s_need   = needv - acc;     // how many to take from bin bsel
            }
        }
        __syncthreads();
        if (lvl == 2) break;

        // rebuild histogram for next level, restricted to current prefix
        hist[tid] = 0;
        __syncthreads();
        const int sh = (lvl == 0) ? 16 : 8;
        const unsigned pf = s_prefix;
        #pragma unroll
        for (int i = 0; i < SLOTS; i++) {
            unsigned u = keysu[i * CTA + tid];
            bool valid = (u >> (sh + 8)) == pf;
            int bin = valid ? (int)((u >> sh) & 255u) : -1;
            unsigned mk = __match_any_sync(0xffffffffu, bin);
            if (valid && ((__ffs(mk) - 1) == lane)) atomicAdd(&hist[bin], __popc(mk));
        }
        __syncthreads();
    }

    // ---- phase 3: collect winners (set only; order irrelevant) + tie list
    {
        const unsigned pf24 = s_prefix;
        #pragma unroll
        for (int i = 0; i < SLOTS; i++) {
            int p = i * CTA + tid;
            unsigned u = keysu[p];
            unsigned hi = u >> 8;
            if (hi > pf24) {
                int pos = atomicAdd(&s_cntW, 1);
                knn_s[pos] = p;
            } else if (hi == pf24) {
                int pos = atomicAdd(&s_cntT, 1);
                if (pos < 64) { tie_idx[pos] = p; tie_key[pos] = u; }
            }
        }
    }
    __syncthreads();

    // resolve threshold bin exactly: take s_need largest (value desc, index asc)
    if (tid == 0) {
        int base  = s_cntW;
        int needf = s_need;
        int cnt   = s_cntT < 64 ? s_cntT : 64;
        for (int r = 0; r < needf; r++) {
            int bj = r;
            for (int j = r + 1; j < cnt; j++)
                if (tie_key[j] > tie_key[bj] ||
                    (tie_key[j] == tie_key[bj] && tie_idx[j] < tie_idx[bj])) bj = j;
            unsigned tk = tie_key[bj]; int ti = tie_idx[bj];
            tie_key[bj] = tie_key[r]; tie_idx[bj] = tie_idx[r];
            tie_key[r] = tk; tie_idx[r] = ti;
            knn_s[base + r] = ti;
        }
    }
    __syncthreads();

    // ---- phase 4: gather neighbor coords
    if (tid < KNN) nbr[tid] = xp[knn_s[tid]];
    __syncthreads();

    // ---- phase 5: edge MLP (6->64) + folded BN + leaky relu + max over K
    if (tid < CO) {
        const int o = tid;
        const float w0 = W[o*6+0], w1 = W[o*6+1], w2 = W[o*6+2];
        const float w3 = W[o*6+3], w4 = W[o*6+4], w5 = W[o*6+5];
        const float inv   = gamma_[o] * rsqrtf(var_[o] + 1e-5f);
        const float shift = beta_[o] - mean_[o] * inv;
        const float cpart = q.x*w3 + q.y*w4 + q.z*w5;

        float m = -3.4028235e38f;
        #pragma unroll
        for (int k = 0; k < KNN; k++) {
            float ex = nbr[k].x - q.x;
            float ey = nbr[k].y - q.y;
            float ez = nbr[k].z - q.z;
            float y  = fmaf(ex, w0, fmaf(ey, w1, fmaf(ez, w2, cpart)));
            y = fmaf(y, inv, shift);
            y = (y >= 0.0f) ? y : 0.2f * y;
            m = fmaxf(m, y);
        }
        out[(size_t)b * CO * NPTS + (size_t)o * NPTS + n] = m;
    }
}

extern "C" void kernel_launch(void* const* d_in, const int* in_sizes, int n_in,
                              void* d_out, int out_size)
{
    const float* x      = (const float*)d_in[0];
    const float* W      = (const float*)d_in[1];
    const float* gamma_ = (const float*)d_in[2];
    const float* beta_  = (const float*)d_in[3];
    const float* mean_  = (const float*)d_in[4];
    const float* var_   = (const float*)d_in[5];
    float* out = (float*)d_out;

    prep_kernel<<<(NB * NPTS + 255) / 256, 256>>>(x);
    dim3 grid(NPTS, NB);
    edgeconv_kernel<<<grid, CTA>>>(W, gamma_, beta_, mean_, var_, out);
}

// round 4
// speedup vs baseline: 3.2389x; 1.0438x over previous
#include <cuda_runtime.h>

#define NPTS 4096
#define NB   8
#define KNN  20
#define CO   64
#define CTA  256
#define SLOTS 16          // keys per thread
#define TIE_CAP 64

__device__ float4 g_xp[NB * NPTS];   // packed {x, y, z, -0.5*|p|^2}

__global__ void prep_kernel(const float* __restrict__ x)
{
    int idx = blockIdx.x * blockDim.x + threadIdx.x;
    if (idx >= NB * NPTS) return;
    int b = idx >> 12, p = idx & (NPTS - 1);
    const float* xb = x + (size_t)b * 3 * NPTS;
    float px = xb[p], py = xb[NPTS + p], pz = xb[2 * NPTS + p];
    g_xp[idx] = make_float4(px, py, pz, -0.5f * (px*px + py*py + pz*pz));
}

// monotone float->uint: preserves ordering, larger float -> larger uint
__device__ __forceinline__ unsigned mono(float f)
{
    unsigned b = __float_as_uint(f);
    return b ^ (unsigned)(((int)b >> 31) | 0x80000000);
}

__global__ __launch_bounds__(CTA)
void edgeconv_kernel(const float* __restrict__ W,      // (64,6)
                     const float* __restrict__ gamma_,
                     const float* __restrict__ beta_,
                     const float* __restrict__ mean_,
                     const float* __restrict__ var_,
                     float* __restrict__ out)          // (B,64,N)
{
    __shared__ int      hist[256];
    __shared__ int      knn_s[KNN];
    __shared__ float4   nbr[KNN];
    __shared__ int      tie_idx[TIE_CAP];
    __shared__ unsigned tie_key[TIE_CAP];
    __shared__ int      s_cntW, s_cntT, s_need, s_cnt, s_bits;
    __shared__ unsigned s_prefix;

    const int b    = blockIdx.y;
    const int n    = blockIdx.x;
    const int tid  = threadIdx.x;
    const int lane = tid & 31;
    const int wid  = tid >> 5;

    const float4* __restrict__ xp = g_xp + (size_t)b * NPTS;
    const float4 q = xp[n];

    hist[tid] = 0;
    if (tid == 0) { s_cntW = 0; s_cntT = 0; s_need = KNN; s_prefix = 0; s_bits = 0; }
    __syncthreads();

    // ---- phase 1: keys (pd/2 as monotone uint) in REGISTERS + level-0 hist (bits 31:24)
    unsigned ku[SLOTS];
    #pragma unroll
    for (int i = 0; i < SLOTS; i++) {
        float4 v = xp[i * CTA + tid];
        float s = q.w + v.w;
        s = fmaf(q.x, v.x, fmaf(q.y, v.y, fmaf(q.z, v.z, s)));
        unsigned u = mono(s);
        ku[i] = u;
        int bin = (int)(u >> 24);
        unsigned mk = __match_any_sync(0xffffffffu, bin);
        if ((__ffs(mk) - 1) == lane) atomicAdd(&hist[bin], __popc(mk));
    }
    __syncthreads();

    // warp-0 suffix-scan + bin select (macro-ish lambda)
    auto scan_select = [&]() {
        if (wid == 0) {
            int base = 255 - lane * 8;
            int c[8];
            int s = 0;
            #pragma unroll
            for (int j = 0; j < 8; j++) { c[j] = hist[base - j]; s += c[j]; }
            int cum = s;
            #pragma unroll
            for (int off = 1; off < 32; off <<= 1) {
                int t = __shfl_up_sync(0xffffffffu, cum, off);
                if (lane >= off) cum += t;
            }
            int needv = s_need;
            __syncwarp();
            int cumBefore = cum - s;
            if (cumBefore < needv && needv <= cum) {
                int acc = cumBefore;
                int bsel = base, csel = c[0];
                #pragma unroll
                for (int j = 0; j < 8; j++) {
                    if (acc + c[j] >= needv) { bsel = base - j; csel = c[j]; break; }
                    acc += c[j];
                }
                s_prefix = (s_prefix << 8) | (unsigned)bsel;
                s_need   = needv - acc;
                s_cnt    = csel;
                s_bits  += 8;
            }
        }
    };

    scan_select();
    __syncthreads();

    // ---- adaptive refinement: only while the threshold bin exceeds tie capacity
    if (s_cnt > TIE_CAP) {                       // level 1 (bits 23:16)
        hist[tid] = 0;
        __syncthreads();
        {
            const unsigned pf = s_prefix;
            #pragma unroll
            for (int i = 0; i < SLOTS; i++) {
                unsigned u = ku[i];
                bool valid = (u >> 24) == pf;
                int bin = valid ? (int)((u >> 16) & 255u) : -1;
                unsigned mk = __match_any_sync(0xffffffffu, bin);
                if (valid && ((__ffs(mk) - 1) == lane)) atomicAdd(&hist[bin], __popc(mk));
            }
        }
        __syncthreads();
        scan_select();
        __syncthreads();

        if (s_cnt > TIE_CAP) {                   // level 2 (bits 15:8)
            hist[tid] = 0;
            __syncthreads();
            {
                const unsigned pf = s_prefix;
                #pragma unroll
                for (int i = 0; i < SLOTS; i++) {
                    unsigned u = ku[i];
                    bool valid = (u >> 16) == pf;
                    int bin = valid ? (int)((u >> 8) & 255u) : -1;
                    unsigned mk = __match_any_sync(0xffffffffu, bin);
                    if (valid && ((__ffs(mk) - 1) == lane)) atomicAdd(&hist[bin], __popc(mk));
                }
            }
            __syncthreads();
            scan_select();
            __syncthreads();
        }
    }

    // ---- collect winners (unordered set) + boundary-bin tie candidates
    {
        const int      sh = 32 - s_bits;         // 24, 16, or 8
        const unsigned pf = s_prefix;
        #pragma unroll
        for (int i = 0; i < SLOTS; i++) {
            unsigned u = ku[i];
            unsigned hi = u >> sh;
            if (hi > pf) {
                knn_s[atomicAdd(&s_cntW, 1)] = i * CTA + tid;
            } else if (hi == pf) {
                int pos = atomicAdd(&s_cntT, 1);
                if (pos < TIE_CAP) { tie_idx[pos] = i * CTA + tid; tie_key[pos] = u; }
            }
        }
    }
    __syncthreads();

    // ---- parallel exact tie resolve: rank by (value desc, index asc)
    {
        int cnt   = s_cntT < TIE_CAP ? s_cntT : TIE_CAP;
        int needf = s_need;
        int baseW = s_cntW;
        if (tid < cnt) {
            unsigned mk = tie_key[tid]; int mi = tie_idx[tid];
            int rank = 0;
            for (int j = 0; j < cnt; j++) {
                unsigned kj = tie_key[j]; int ij = tie_idx[j];
                rank += (kj > mk) || (kj == mk && ij < mi);
            }
            if (rank < needf) knn_s[baseW + rank] = mi;
        }
    }
    __syncthreads();

    // ---- gather neighbor coords
    if (tid < KNN) nbr[tid] = xp[knn_s[tid]];
    __syncthreads();

    // ---- edge MLP (6->64) + folded BN + leaky relu + max over K
    if (tid < CO) {
        const int o = tid;
        const float w0 = __ldg(&W[o*6+0]), w1 = __ldg(&W[o*6+1]), w2 = __ldg(&W[o*6+2]);
        const float w3 = __ldg(&W[o*6+3]), w4 = __ldg(&W[o*6+4]), w5 = __ldg(&W[o*6+5]);
        const float inv   = __ldg(&gamma_[o]) * rsqrtf(__ldg(&var_[o]) + 1e-5f);
        const float shift = __ldg(&beta_[o]) - __ldg(&mean_[o]) * inv;
        const float cpart = q.x*w3 + q.y*w4 + q.z*w5;

        float m = -3.4028235e38f;
        #pragma unroll
        for (int k = 0; k < KNN; k++) {
            float ex = nbr[k].x - q.x;
            float ey = nbr[k].y - q.y;
            float ez = nbr[k].z - q.z;
            float y  = fmaf(ex, w0, fmaf(ey, w1, fmaf(ez, w2, cpart)));
            y = fmaf(y, inv, shift);
            y = (y >= 0.0f) ? y : 0.2f * y;
            m = fmaxf(m, y);
        }
        out[(size_t)b * CO * NPTS + (size_t)o * NPTS + n] = m;
    }
}

extern "C" void kernel_launch(void* const* d_in, const int* in_sizes, int n_in,
                              void* d_out, int out_size)
{
    const float* x      = (const float*)d_in[0];
    const float* W      = (const float*)d_in[1];
    const float* gamma_ = (const float*)d_in[2];
    const float* beta_  = (const float*)d_in[3];
    const float* mean_  = (const float*)d_in[4];
    const float* var_   = (const float*)d_in[5];
    float* out = (float*)d_out;

    prep_kernel<<<(NB * NPTS + 255) / 256, 256>>>(x);
    dim3 grid(NPTS, NB);
    edgeconv_kernel<<<grid, CTA>>>(W, gamma_, beta_, mean_, var_, out);
}